// round 2
// baseline (speedup 1.0000x reference)
#include <cuda_runtime.h>
#include <cuda_bf16.h>

// TemporalGCN: per (b,t): h = relu(Linear(A@h)) x2, then mean over node dim.
// B=32, T=512, C=22, FREQ=192, HID=128.
// One CTA of 128 threads per (b,t). Thread h owns hidden column h.
// All intermediates in smem (transposed, row-stride 28 for conflict-free
// broadcast LDS.128) or registers. Weights streamed from L2 via LDG.128.

#define CN 22    // nodes
#define FN 192   // input freq
#define HN 128   // hidden
#define CP 28    // padded row stride (floats): 8-lane 128-bit phases conflict-free

__global__ __launch_bounds__(128, 4) void tgcn_kernel(
    const float* __restrict__ x, const float* __restrict__ A,
    const float* __restrict__ W0, const float* __restrict__ b0,
    const float* __restrict__ W1, const float* __restrict__ b1,
    float* __restrict__ out)
{
    __shared__ float sA [CN * CP];   // A rows, padded
    __shared__ float sXT[FN * CP];   // x transposed: [f][j]; later reused as y1^T [k][c]
    __shared__ float sYT[FN * CP];   // y0 transposed: [f][c]

    const int bt  = blockIdx.x;
    const int tid = threadIdx.x;
    const float* xg = x + (size_t)bt * (CN * FN);
    const float* Ag = A + (size_t)bt * (CN * CN);

    // ---- load x (transposed) and A into smem ----
    for (int idx = tid; idx < CN * FN; idx += 128) {
        int j = idx / FN;
        int f = idx - j * FN;
        sXT[f * CP + j] = xg[idx];
    }
    for (int idx = tid; idx < CN * CN; idx += 128) {
        int c = idx / CN;
        int j = idx - c * CN;
        sA[c * CP + j] = Ag[idx];
    }
    const float bias0 = __ldg(b0 + tid);
    const float bias1 = __ldg(b1 + tid);
    __syncthreads();

    // ---- stage 1: y0 = A @ x  -> sYT[f][c] ----
    // 4224 elements / 128 threads = 33 per thread
    #pragma unroll 1
    for (int i = 0; i < (CN * FN) / 128; i++) {
        int e = tid + i * 128;
        int c = e / FN;
        int f = e - c * FN;
        const float* ar = sA  + c * CP;
        const float* xr = sXT + f * CP;
        float s0 = 0.f, s1 = 0.f, s2 = 0.f, s3 = 0.f;
        #pragma unroll
        for (int j = 0; j < 20; j += 4) {
            float4 a4 = *reinterpret_cast<const float4*>(ar + j);
            float4 x4 = *reinterpret_cast<const float4*>(xr + j);
            s0 = fmaf(a4.x, x4.x, s0);
            s1 = fmaf(a4.y, x4.y, s1);
            s2 = fmaf(a4.z, x4.z, s2);
            s3 = fmaf(a4.w, x4.w, s3);
        }
        s0 = fmaf(ar[20], xr[20], s0);
        s1 = fmaf(ar[21], xr[21], s1);
        sYT[f * CP + c] = (s0 + s1) + (s2 + s3);
    }
    __syncthreads();

    // ---- stage 2: h0[:, tid] = relu(y0 @ W0^T + b0) ----
    float acc[CN];
    #pragma unroll
    for (int c = 0; c < CN; c++) acc[c] = 0.f;
    {
        const float4* wr = reinterpret_cast<const float4*>(W0 + (size_t)tid * FN);
        #pragma unroll 2
        for (int k4 = 0; k4 < FN / 4; k4++) {
            float4 w4 = __ldg(wr + k4);
            const float* yb = sYT + (k4 * 4) * CP;
            #pragma unroll
            for (int kk = 0; kk < 4; kk++) {
                float w = (kk == 0) ? w4.x : (kk == 1) ? w4.y : (kk == 2) ? w4.z : w4.w;
                const float* yr = yb + kk * CP;
                #pragma unroll
                for (int c4 = 0; c4 < 20; c4 += 4) {
                    float4 yv = *reinterpret_cast<const float4*>(yr + c4);
                    acc[c4 + 0] = fmaf(yv.x, w, acc[c4 + 0]);
                    acc[c4 + 1] = fmaf(yv.y, w, acc[c4 + 1]);
                    acc[c4 + 2] = fmaf(yv.z, w, acc[c4 + 2]);
                    acc[c4 + 3] = fmaf(yv.w, w, acc[c4 + 3]);
                }
                float2 yt = *reinterpret_cast<const float2*>(yr + 20);
                acc[20] = fmaf(yt.x, w, acc[20]);
                acc[21] = fmaf(yt.y, w, acc[21]);
            }
        }
    }
    float h0[CN];
    #pragma unroll
    for (int c = 0; c < CN; c++) h0[c] = fmaxf(acc[c] + bias0, 0.f);

    // ---- stage 3: y1[:, tid] = A @ h0[:, tid]  (registers only) -> sZT[tid][c] ----
    float y1buf[CN];
    #pragma unroll
    for (int c = 0; c < CN; c++) {
        const float* ar = sA + c * CP;
        float s0 = 0.f, s1 = 0.f, s2 = 0.f, s3 = 0.f;
        #pragma unroll
        for (int j = 0; j < 20; j += 4) {
            float4 a4 = *reinterpret_cast<const float4*>(ar + j);
            s0 = fmaf(a4.x, h0[j + 0], s0);
            s1 = fmaf(a4.y, h0[j + 1], s1);
            s2 = fmaf(a4.z, h0[j + 2], s2);
            s3 = fmaf(a4.w, h0[j + 3], s3);
        }
        s0 = fmaf(ar[20], h0[20], s0);
        s1 = fmaf(ar[21], h0[21], s1);
        y1buf[c] = (s0 + s1) + (s2 + s3);
    }
    float* sZT = sXT;  // reuse x buffer (no reader after stage-1 barrier)
    {
        float* zr = sZT + tid * CP;
        #pragma unroll
        for (int c = 0; c < 20; c += 4)
            *reinterpret_cast<float4*>(zr + c) =
                make_float4(y1buf[c], y1buf[c + 1], y1buf[c + 2], y1buf[c + 3]);
        *reinterpret_cast<float2*>(zr + 20) = make_float2(y1buf[20], y1buf[21]);
    }
    __syncthreads();

    // ---- stage 4: h1[:, tid] = relu(y1 @ W1^T + b1) ----
    #pragma unroll
    for (int c = 0; c < CN; c++) acc[c] = 0.f;
    {
        const float4* wr = reinterpret_cast<const float4*>(W1 + (size_t)tid * HN);
        #pragma unroll 2
        for (int k4 = 0; k4 < HN / 4; k4++) {
            float4 w4 = __ldg(wr + k4);
            const float* yb = sZT + (k4 * 4) * CP;
            #pragma unroll
            for (int kk = 0; kk < 4; kk++) {
                float w = (kk == 0) ? w4.x : (kk == 1) ? w4.y : (kk == 2) ? w4.z : w4.w;
                const float* yr = yb + kk * CP;
                #pragma unroll
                for (int c4 = 0; c4 < 20; c4 += 4) {
                    float4 yv = *reinterpret_cast<const float4*>(yr + c4);
                    acc[c4 + 0] = fmaf(yv.x, w, acc[c4 + 0]);
                    acc[c4 + 1] = fmaf(yv.y, w, acc[c4 + 1]);
                    acc[c4 + 2] = fmaf(yv.z, w, acc[c4 + 2]);
                    acc[c4 + 3] = fmaf(yv.w, w, acc[c4 + 3]);
                }
                float2 yt = *reinterpret_cast<const float2*>(yr + 20);
                acc[20] = fmaf(yt.x, w, acc[20]);
                acc[21] = fmaf(yt.y, w, acc[21]);
            }
        }
    }

    // ---- stage 5: mean over nodes ----
    float s = 0.f;
    #pragma unroll
    for (int c = 0; c < CN; c++) s += fmaxf(acc[c] + bias1, 0.f);
    out[(size_t)bt * HN + tid] = s * (1.0f / 22.0f);
}

extern "C" void kernel_launch(void* const* d_in, const int* in_sizes, int n_in,
                              void* d_out, int out_size) {
    const float* x  = (const float*)d_in[0];
    const float* A  = (const float*)d_in[1];
    const float* W0 = (const float*)d_in[2];
    const float* b0 = (const float*)d_in[3];
    const float* W1 = (const float*)d_in[4];
    const float* b1 = (const float*)d_in[5];
    float* out = (float*)d_out;

    const int BT = in_sizes[1] / (CN * CN);  // A has BT*22*22 elements -> 16384
    tgcn_kernel<<<BT, 128>>>(x, A, W0, b0, W1, b1, out);
}

// round 4
// speedup vs baseline: 3.0099x; 3.0099x over previous
#include <cuda_runtime.h>
#include <cuda_fp16.h>
#include <cuda_bf16.h>
#include <cstdint>
#include <cstddef>

#define CN 22
#define FN 192
#define HN 128
#define BT_TOT 16384
#define NROWS (BT_TOT * CN)          // 360448, = 2816 * 128 exactly

// fp32 scratch for U/V and H
__device__ float g_U[(size_t)NROWS * HN];
__device__ float g_H[(size_t)NROWS * HN];
// weights pre-split to bf16 hi/lo in MMA-fragment order:
// t = s*512 + f*32 + lane  ->  uint4{hi_b0, hi_b1, lo_b0, lo_b1}
__device__ uint4 g_W0s[(FN / 16) * 16 * 32];
__device__ uint4 g_W1s[(HN / 16) * 16 * 32];

__device__ __forceinline__ uint32_t pack_bf16(float x, float y) {
    __nv_bfloat162 p;
    p.x = __float2bfloat16(x);
    p.y = __float2bfloat16(y);
    return *reinterpret_cast<uint32_t*>(&p);
}
__device__ __forceinline__ uint32_t pack_bf16_resid(float x, float y, uint32_t hi) {
    __nv_bfloat162 h = *reinterpret_cast<__nv_bfloat162*>(&hi);
    return pack_bf16(x - __bfloat162float(h.x), y - __bfloat162float(h.y));
}

// ---- weight prep: W [128][K] fp32 -> fragment-order split bf16 ----
__global__ void prep_w(const float* __restrict__ W, int K, uint4* __restrict__ out) {
    int t = blockIdx.x * blockDim.x + threadIdx.x;
    int total = (K / 16) * 16 * 32;
    if (t >= total) return;
    int l = t & 31;
    int f = (t >> 5) & 15;
    int s = t >> 9;
    int n = f * 8 + (l >> 2);
    int k0 = s * 16 + (l & 3) * 2;
    const float* wr = W + (size_t)n * K;
    float w00 = wr[k0], w01 = wr[k0 + 1], w10 = wr[k0 + 8], w11 = wr[k0 + 9];
    uint32_t h0 = pack_bf16(w00, w01), h1 = pack_bf16(w10, w11);
    uint32_t l0 = pack_bf16_resid(w00, w01, h0), l1 = pack_bf16_resid(w10, w11, h1);
    out[t] = make_uint4(h0, h1, l0, l1);
}

// ---- mma.sync m16n8k16 row.col bf16 -> f32 ----
__device__ __forceinline__ void mma_bf16(float* c, const uint32_t* a, uint32_t b0, uint32_t b1) {
    asm volatile(
        "mma.sync.aligned.m16n8k16.row.col.f32.bf16.bf16.f32 "
        "{%0,%1,%2,%3}, {%4,%5,%6,%7}, {%8,%9}, {%0,%1,%2,%3};"
        : "+f"(c[0]), "+f"(c[1]), "+f"(c[2]), "+f"(c[3])
        : "r"(a[0]), "r"(a[1]), "r"(a[2]), "r"(a[3]), "r"(b0), "r"(b1));
}

// ---- GEMM: dst[M,128] = src[M,K] @ W[128,K]^T, 3-term bf16 split ----
// Tile 128x128 per CTA, 8 warps as 4M x 2N -> warp tile 32x64.
#define XPAD 40
template <int K>
__global__ void __launch_bounds__(256) gemm_ms(
    const float* __restrict__ src, const uint4* __restrict__ Ws, float* __restrict__ dst)
{
    __shared__ float sX[128 * XPAD];       // 20.5 KB, padded rows (conflict-free LDS.64)
    __shared__ uint4 sW[2 * 16 * 32];      // 16 KB: one K32 chunk, fragment order

    const int tid = threadIdx.x;
    const int wid = tid >> 5, l = tid & 31;
    const int wm = wid & 3, wn = wid >> 2;   // warp grid 4M x 2N
    const int g = l >> 2, q = l & 3;
    const int row0 = blockIdx.x * 128;

    float acc[2][8][4];
#pragma unroll
    for (int mf = 0; mf < 2; mf++)
#pragma unroll
        for (int f = 0; f < 8; f++)
#pragma unroll
            for (int i = 0; i < 4; i++) acc[mf][f][i] = 0.f;

#pragma unroll 1
    for (int kc = 0; kc < K / 32; kc++) {
        // stage activations: 128 rows x 32 cols fp32
#pragma unroll
        for (int i = 0; i < 4; i++) {
            int u = tid + i * 256;            // 1024 float4 units
            int r = u >> 3, c4 = u & 7;
            float4 v = *reinterpret_cast<const float4*>(
                src + (size_t)(row0 + r) * K + kc * 32 + c4 * 4);
            *reinterpret_cast<float4*>(&sX[r * XPAD + c4 * 4]) = v;
        }
        // stage weight chunk: contiguous 1024 uint4
#pragma unroll
        for (int i = 0; i < 4; i++) {
            int u = tid + i * 256;
            sW[u] = Ws[kc * 1024 + u];
        }
        __syncthreads();

#pragma unroll
        for (int sp = 0; sp < 2; sp++) {      // two k16 steps per chunk
            uint32_t ah[2][4], al[2][4];
#pragma unroll
            for (int mf = 0; mf < 2; mf++) {
                int r = wm * 32 + mf * 16 + g;
                int kb = sp * 16 + q * 2;
                float2 aa = *reinterpret_cast<const float2*>(&sX[r * XPAD + kb]);
                float2 ab = *reinterpret_cast<const float2*>(&sX[r * XPAD + kb + 8]);
                float2 ba = *reinterpret_cast<const float2*>(&sX[(r + 8) * XPAD + kb]);
                float2 bb = *reinterpret_cast<const float2*>(&sX[(r + 8) * XPAD + kb + 8]);
                ah[mf][0] = pack_bf16(aa.x, aa.y);
                ah[mf][1] = pack_bf16(ba.x, ba.y);
                ah[mf][2] = pack_bf16(ab.x, ab.y);
                ah[mf][3] = pack_bf16(bb.x, bb.y);
                al[mf][0] = pack_bf16_resid(aa.x, aa.y, ah[mf][0]);
                al[mf][1] = pack_bf16_resid(ba.x, ba.y, ah[mf][1]);
                al[mf][2] = pack_bf16_resid(ab.x, ab.y, ah[mf][2]);
                al[mf][3] = pack_bf16_resid(bb.x, bb.y, ah[mf][3]);
            }
#pragma unroll
            for (int f = 0; f < 8; f++) {
                uint4 bv = sW[(size_t)(sp * 16 + wn * 8 + f) * 32 + l];
#pragma unroll
                for (int mf = 0; mf < 2; mf++) {
                    mma_bf16(acc[mf][f], ah[mf], bv.x, bv.y);   // Ahi * Bhi
                    mma_bf16(acc[mf][f], al[mf], bv.x, bv.y);   // Alo * Bhi
                    mma_bf16(acc[mf][f], ah[mf], bv.z, bv.w);   // Ahi * Blo
                }
            }
        }
        __syncthreads();
    }

    // epilogue: fp32 store
#pragma unroll
    for (int mf = 0; mf < 2; mf++) {
        int r = row0 + wm * 32 + mf * 16 + g;
#pragma unroll
        for (int f = 0; f < 8; f++) {
            int cb = wn * 64 + f * 8 + q * 2;
            *reinterpret_cast<float2*>(&dst[(size_t)r * HN + cb]) =
                make_float2(acc[mf][f][0], acc[mf][f][1]);
            *reinterpret_cast<float2*>(&dst[(size_t)(r + 8) * HN + cb]) =
                make_float2(acc[mf][f][2], acc[mf][f][3]);
        }
    }
}

// ---------------- mix kernels (per-bt 22x22 adjacency, fp32) ----------------
__global__ void __launch_bounds__(128) mix_relu(
    const float* __restrict__ A, const float* __restrict__ U,
    const float* __restrict__ bias, float* __restrict__ H)
{
    __shared__ float sA[CN * CN];
    const int bt = blockIdx.x, h = threadIdx.x;
    const float* Ag = A + (size_t)bt * (CN * CN);
    for (int i = h; i < CN * CN; i += 128) sA[i] = Ag[i];
    float u[CN];
    const float* Ub = U + (size_t)bt * (CN * HN) + h;
#pragma unroll
    for (int j = 0; j < CN; j++) u[j] = Ub[j * HN];
    const float bh = bias[h];
    __syncthreads();
    float* Hb = H + (size_t)bt * (CN * HN) + h;
#pragma unroll
    for (int c = 0; c < CN; c++) {
        const float* ar = sA + c * CN;
        float s = 0.f;
#pragma unroll
        for (int j = 0; j < CN; j++) s = fmaf(ar[j], u[j], s);
        Hb[c * HN] = fmaxf(s + bh, 0.f);
    }
}

__global__ void __launch_bounds__(128) mix_relu_mean(
    const float* __restrict__ A, const float* __restrict__ V,
    const float* __restrict__ bias, float* __restrict__ out)
{
    __shared__ float sA[CN * CN];
    const int bt = blockIdx.x, h = threadIdx.x;
    const float* Ag = A + (size_t)bt * (CN * CN);
    for (int i = h; i < CN * CN; i += 128) sA[i] = Ag[i];
    float u[CN];
    const float* Vb = V + (size_t)bt * (CN * HN) + h;
#pragma unroll
    for (int j = 0; j < CN; j++) u[j] = Vb[j * HN];
    const float bh = bias[h];
    __syncthreads();
    float tot = 0.f;
#pragma unroll
    for (int c = 0; c < CN; c++) {
        const float* ar = sA + c * CN;
        float s = 0.f;
#pragma unroll
        for (int j = 0; j < CN; j++) s = fmaf(ar[j], u[j], s);
        tot += fmaxf(s + bh, 0.f);
    }
    out[(size_t)bt * HN + h] = tot * (1.0f / (float)CN);
}

// ---------------- launch ----------------
extern "C" void kernel_launch(void* const* d_in, const int* in_sizes, int n_in,
                              void* d_out, int out_size) {
    const float* x  = (const float*)d_in[0];
    const float* A  = (const float*)d_in[1];
    const float* W0 = (const float*)d_in[2];
    const float* b0 = (const float*)d_in[3];
    const float* W1 = (const float*)d_in[4];
    const float* b1 = (const float*)d_in[5];
    float* out = (float*)d_out;

    const int BT = in_sizes[1] / (CN * CN);      // 16384
    const int mtiles = (BT * CN) / 128;          // 2816

    void *pU = nullptr, *pH = nullptr, *pW0 = nullptr, *pW1 = nullptr;
    cudaGetSymbolAddress(&pU, g_U);
    cudaGetSymbolAddress(&pH, g_H);
    cudaGetSymbolAddress(&pW0, g_W0s);
    cudaGetSymbolAddress(&pW1, g_W1s);
    float* U = (float*)pU;
    float* H = (float*)pH;
    uint4* W0s = (uint4*)pW0;
    uint4* W1s = (uint4*)pW1;

    const int n0 = (FN / 16) * 16 * 32;          // 6144
    const int n1 = (HN / 16) * 16 * 32;          // 4096
    prep_w<<<(n0 + 255) / 256, 256>>>(W0, FN, W0s);
    prep_w<<<(n1 + 255) / 256, 256>>>(W1, HN, W1s);

    // layer 1: U = x @ W0^T ; H = relu(A @ U + b0)
    gemm_ms<FN><<<mtiles, 256>>>(x, W0s, U);
    mix_relu<<<BT, 128>>>(A, U, b0, H);
    // layer 2: V = H @ W1^T (into U) ; out = mean_c relu(A @ V + b1)
    gemm_ms<HN><<<mtiles, 256>>>(H, W1s, U);
    mix_relu_mean<<<BT, 128>>>(A, U, b1, out);
}